// round 2
// baseline (speedup 1.0000x reference)
#include <cuda_runtime.h>
#include <math.h>

// Problem constants (fixed by the reference: B=2, S=2048, H=1024, E=8, I=4096, K=2)
#define Tn 4096
#define Hd 1024
#define Id 4096
#define Ed 8

// ---------------- device scratch (allocation-free rule: static globals) ----------------
__device__ int   g_count[Ed];
__device__ int   g_count2[Ed];
__device__ int   g_offset[Ed];
__device__ int   g_top_e[Tn * 2];
__device__ float g_top_w[Tn * 2];
__device__ int   g_row_tok[Tn * 2];   // compact row -> token id
__device__ int   g_tok_row[Tn * 2];   // token,slot -> compact row
__device__ float g_hidden[(size_t)Tn * 2 * Id];  // 8192 x 4096 fp32 = 134 MB
__device__ float g_down[(size_t)Tn * 2 * Hd];    // 8192 x 1024 fp32 = 33.5 MB

// ---------------- init: zero the per-launch atomic counters ----------------
__global__ void k_init() {
    int i = threadIdx.x;
    if (i < Ed) { g_count[i] = 0; g_count2[i] = 0; }
}

// ---------------- router: warp per token, gate_w resident in smem ----------------
__global__ void __launch_bounds__(256) k_router(const float* __restrict__ x,
                                                const float* __restrict__ gw) {
    __shared__ float sgw[Ed * Hd];  // 32 KB
    int tid = threadIdx.x;
    for (int i = tid; i < Ed * Hd; i += 256) sgw[i] = gw[i];
    __syncthreads();

    int warp = tid >> 5, lane = tid & 31;
    int t = blockIdx.x * 8 + warp;

    float acc[Ed];
#pragma unroll
    for (int e = 0; e < Ed; e++) acc[e] = 0.f;

    const float* xr = x + (size_t)t * Hd;
    for (int h = lane; h < Hd; h += 32) {
        float xv = xr[h];
#pragma unroll
        for (int e = 0; e < Ed; e++) acc[e] += xv * sgw[e * Hd + h];
    }
#pragma unroll
    for (int e = 0; e < Ed; e++) {
#pragma unroll
        for (int o = 16; o > 0; o >>= 1) acc[e] += __shfl_xor_sync(0xffffffffu, acc[e], o);
    }
    if (lane == 0) {
        // top-2 (ties -> lowest index, matching lax.top_k)
        float v0 = -1e30f; int e0 = 0;
#pragma unroll
        for (int e = 0; e < Ed; e++) if (acc[e] > v0) { v0 = acc[e]; e0 = e; }
        float v1 = -1e30f; int e1 = 0;
#pragma unroll
        for (int e = 0; e < Ed; e++) if (e != e0 && acc[e] > v1) { v1 = acc[e]; e1 = e; }
        float r  = expf(v1 - v0);
        float w0 = 1.f / (1.f + r);
        float w1 = r / (1.f + r);
        g_top_e[t * 2]     = e0;  g_top_e[t * 2 + 1] = e1;
        g_top_w[t * 2]     = w0;  g_top_w[t * 2 + 1] = w1;
        atomicAdd(&g_count[e0], 1);
        atomicAdd(&g_count[e1], 1);
    }
}

// ---------------- exclusive scan over 8 counts ----------------
__global__ void k_scan() {
    int off = 0;
    for (int e = 0; e < Ed; e++) { g_offset[e] = off; off += g_count[e]; }
}

// ---------------- assign compact rows (placement nondeterministic, values deterministic) --
__global__ void __launch_bounds__(256) k_assign() {
    int t = blockIdx.x * 256 + threadIdx.x;
    if (t >= Tn) return;
#pragma unroll
    for (int k = 0; k < 2; k++) {
        int e   = g_top_e[t * 2 + k];
        int pos = atomicAdd(&g_count2[e], 1);
        int row = g_offset[e] + pos;
        g_row_tok[row]        = t;
        g_tok_row[t * 2 + k]  = row;
    }
}

// ---------------- GEMM1: hidden = silu(x@wg^T) * (x@wu^T), gathered rows ----------------
// Tile: 128(m) x 64(n) x 16(k), 256 threads, thread computes 8x4 for gate AND up.
__global__ void __launch_bounds__(256) k_gemm1(const float* __restrict__ x,
                                               const float* __restrict__ wg,
                                               const float* __restrict__ wu) {
    int e   = blockIdx.z;
    int cnt = g_count[e];
    int m0  = blockIdx.x * 128;
    if (m0 >= cnt) return;
    int off = g_offset[e];
    int n0  = blockIdx.y * 64;

    __shared__ float As[16][129];
    __shared__ float Bg[16][65];
    __shared__ float Bu[16][65];
    __shared__ int   toks[128];

    int tid = threadIdx.x;
    if (tid < 128) {
        int m = m0 + tid;
        if (m >= cnt) m = cnt - 1;   // clamp to a valid row (result discarded)
        toks[tid] = g_row_tok[off + m];
    }
    __syncthreads();

    int lmA = tid & 127;             // 0..127 (A row)
    int lkA = (tid >> 7) * 8;        // 0 or 8  (A k-offset, 8 floats)
    int lmB = tid >> 2;              // 0..63   (B row)
    int lkB = (tid & 3) * 4;         // 0,4,8,12

    const float* xrow = x  + (size_t)toks[lmA] * Hd + lkA;
    const float* grow = wg + (size_t)e * Id * Hd + (size_t)(n0 + lmB) * Hd + lkB;
    const float* urow = wu + (size_t)e * Id * Hd + (size_t)(n0 + lmB) * Hd + lkB;

    int ty = tid >> 4;               // 0..15 (m groups: ty + i*16)
    int tx = tid & 15;               // 0..15 (n groups: tx + j*16)

    float cg[8][4] = {}, cu[8][4] = {};

    for (int k0 = 0; k0 < Hd; k0 += 16) {
        float4 a0 = *(const float4*)(xrow + k0);
        float4 a1 = *(const float4*)(xrow + k0 + 4);
        float4 gv = *(const float4*)(grow + k0);
        float4 uv = *(const float4*)(urow + k0);
        As[lkA + 0][lmA] = a0.x; As[lkA + 1][lmA] = a0.y;
        As[lkA + 2][lmA] = a0.z; As[lkA + 3][lmA] = a0.w;
        As[lkA + 4][lmA] = a1.x; As[lkA + 5][lmA] = a1.y;
        As[lkA + 6][lmA] = a1.z; As[lkA + 7][lmA] = a1.w;
        Bg[lkB + 0][lmB] = gv.x; Bg[lkB + 1][lmB] = gv.y;
        Bg[lkB + 2][lmB] = gv.z; Bg[lkB + 3][lmB] = gv.w;
        Bu[lkB + 0][lmB] = uv.x; Bu[lkB + 1][lmB] = uv.y;
        Bu[lkB + 2][lmB] = uv.z; Bu[lkB + 3][lmB] = uv.w;
        __syncthreads();
#pragma unroll
        for (int kk = 0; kk < 16; kk++) {
            float a[8], bg[4], bu[4];
#pragma unroll
            for (int i = 0; i < 8; i++) a[i] = As[kk][ty + i * 16];
#pragma unroll
            for (int j = 0; j < 4; j++) { bg[j] = Bg[kk][tx + j * 16]; bu[j] = Bu[kk][tx + j * 16]; }
#pragma unroll
            for (int i = 0; i < 8; i++)
#pragma unroll
                for (int j = 0; j < 4; j++) {
                    cg[i][j] += a[i] * bg[j];
                    cu[i][j] += a[i] * bu[j];
                }
        }
        __syncthreads();
    }

    // epilogue: silu(g) * u
#pragma unroll
    for (int i = 0; i < 8; i++) {
        int m = ty + i * 16;
        if (m0 + m < cnt) {
            size_t rbase = (size_t)(off + m0 + m) * Id + n0;
#pragma unroll
            for (int j = 0; j < 4; j++) {
                int n = tx + j * 16;
                float g = cg[i][j];
                float h = g / (1.f + expf(-g)) * cu[i][j];
                g_hidden[rbase + n] = h;
            }
        }
    }
}

// ---------------- GEMM2: down = hidden @ wd^T ----------------
// Tile: 128(m) x 128(n) x 16(k), 256 threads, thread computes 8x8.
__global__ void __launch_bounds__(256) k_gemm2(const float* __restrict__ wd) {
    int e   = blockIdx.z;
    int cnt = g_count[e];
    int m0  = blockIdx.x * 128;
    if (m0 >= cnt) return;
    int off = g_offset[e];
    int n0  = blockIdx.y * 128;

    __shared__ float As[16][129];
    __shared__ float Bs[16][129];

    int tid = threadIdx.x;
    int lmA = tid & 127;             // 0..127
    int lkA = (tid >> 7) * 8;        // 0 or 8
    int am  = m0 + lmA; if (am >= cnt) am = cnt - 1;

    const float* arow = g_hidden + (size_t)(off + am) * Id + lkA;
    const float* brow = wd + (size_t)e * Hd * Id + (size_t)(n0 + lmA) * Id + lkA;

    int ty = tid >> 4;               // 0..15
    int tx = tid & 15;               // 0..15

    float c[8][8] = {};

    for (int k0 = 0; k0 < Id; k0 += 16) {
        float4 a0 = *(const float4*)(arow + k0);
        float4 a1 = *(const float4*)(arow + k0 + 4);
        float4 b0 = *(const float4*)(brow + k0);
        float4 b1 = *(const float4*)(brow + k0 + 4);
        As[lkA + 0][lmA] = a0.x; As[lkA + 1][lmA] = a0.y;
        As[lkA + 2][lmA] = a0.z; As[lkA + 3][lmA] = a0.w;
        As[lkA + 4][lmA] = a1.x; As[lkA + 5][lmA] = a1.y;
        As[lkA + 6][lmA] = a1.z; As[lkA + 7][lmA] = a1.w;
        Bs[lkA + 0][lmA] = b0.x; Bs[lkA + 1][lmA] = b0.y;
        Bs[lkA + 2][lmA] = b0.z; Bs[lkA + 3][lmA] = b0.w;
        Bs[lkA + 4][lmA] = b1.x; Bs[lkA + 5][lmA] = b1.y;
        Bs[lkA + 6][lmA] = b1.z; Bs[lkA + 7][lmA] = b1.w;
        __syncthreads();
#pragma unroll
        for (int kk = 0; kk < 16; kk++) {
            float a[8], b[8];
#pragma unroll
            for (int i = 0; i < 8; i++) a[i] = As[kk][ty + i * 16];
#pragma unroll
            for (int j = 0; j < 8; j++) b[j] = Bs[kk][tx + j * 16];
#pragma unroll
            for (int i = 0; i < 8; i++)
#pragma unroll
                for (int j = 0; j < 8; j++) c[i][j] += a[i] * b[j];
        }
        __syncthreads();
    }

#pragma unroll
    for (int i = 0; i < 8; i++) {
        int m = ty + i * 16;
        if (m0 + m < cnt) {
            size_t base = (size_t)(off + m0 + m) * Hd + n0;
#pragma unroll
            for (int j = 0; j < 8; j++) g_down[base + tx + j * 16] = c[i][j];
        }
    }
}

// ---------------- combine: out[t] = w0*down[row0] + w1*down[row1] ----------------
__global__ void __launch_bounds__(256) k_combine(float* __restrict__ out) {
    int idx = blockIdx.x * 256 + threadIdx.x;       // over Tn*Hd/4 float4s
    int t   = idx >> 8;                              // Hd/4 = 256 vec4 per token
    int c4  = (idx & 255) << 2;
    int r0  = g_tok_row[t * 2];
    int r1  = g_tok_row[t * 2 + 1];
    float w0 = g_top_w[t * 2];
    float w1 = g_top_w[t * 2 + 1];
    float4 d0 = *(const float4*)(g_down + (size_t)r0 * Hd + c4);
    float4 d1 = *(const float4*)(g_down + (size_t)r1 * Hd + c4);
    float4 o;
    o.x = w0 * d0.x + w1 * d1.x;
    o.y = w0 * d0.y + w1 * d1.y;
    o.z = w0 * d0.z + w1 * d1.z;
    o.w = w0 * d0.w + w1 * d1.w;
    *(float4*)(out + (size_t)t * Hd + c4) = o;
}

// ---------------- launch ----------------
extern "C" void kernel_launch(void* const* d_in, const int* in_sizes, int n_in,
                              void* d_out, int out_size) {
    const float* x  = (const float*)d_in[0];
    const float* gw = (const float*)d_in[1];
    const float* wg = (const float*)d_in[2];
    const float* wu = (const float*)d_in[3];
    const float* wd = (const float*)d_in[4];
    float* out = (float*)d_out;

    k_init<<<1, 32>>>();
    k_router<<<Tn / 8, 256>>>(x, gw);
    k_scan<<<1, 1>>>();
    k_assign<<<Tn / 256, 256>>>();

    dim3 g1(Tn / 128, Id / 64, Ed);      // 32 x 64 x 8, early-exit on count
    k_gemm1<<<g1, 256>>>(x, wg, wu);

    dim3 g2(Tn / 128, Hd / 128, Ed);     // 32 x 8 x 8, early-exit on count
    k_gemm2<<<g2, 256>>>(wd);

    k_combine<<<Tn * Hd / 1024, 256>>>(out);
}

// round 5
// speedup vs baseline: 3.8396x; 3.8396x over previous
#include <cuda_runtime.h>
#include <math.h>
#include <stdint.h>

// Problem constants (B=2, S=2048, H=1024, E=8, I=4096, K=2)
#define Tn 4096
#define Hd 1024
#define Id 4096
#define Ed 8

// ---------------- device scratch ----------------
__device__ int   g_count[Ed];
__device__ int   g_count2[Ed];
__device__ int   g_offset[Ed];
__device__ int   g_top_e[Tn * 2];
__device__ float g_top_w[Tn * 2];
__device__ int   g_row_tok[Tn * 2];
__device__ int   g_tok_row[Tn * 2];
__device__ float g_hidden[(size_t)Tn * 2 * Id];  // 134 MB
__device__ float g_down[(size_t)Tn * 2 * Hd];    // 33.5 MB

// ---------------- helpers ----------------
__device__ __forceinline__ uint32_t f2tf32(float f) {
    uint32_t r; asm("cvt.rna.tf32.f32 %0, %1;" : "=r"(r) : "f"(f)); return r;
}
__device__ __forceinline__ uint4 tf4(float4 v) {
    uint4 u; u.x = f2tf32(v.x); u.y = f2tf32(v.y); u.z = f2tf32(v.z); u.w = f2tf32(v.w);
    return u;
}
// D += A(16x8,row) * B(8x8,col)  tf32
#define MMA_TF32(c, a, b0, b1) \
    asm volatile("mma.sync.aligned.m16n8k8.row.col.f32.tf32.tf32.f32 " \
                 "{%0,%1,%2,%3}, {%4,%5,%6,%7}, {%8,%9}, {%0,%1,%2,%3};" \
                 : "+f"((c)[0]), "+f"((c)[1]), "+f"((c)[2]), "+f"((c)[3]) \
                 : "r"((a)[0]), "r"((a)[1]), "r"((a)[2]), "r"((a)[3]), \
                   "r"(b0), "r"(b1))

// ---------------- init / router / scan / assign ----------------
__global__ void k_init() {
    int i = threadIdx.x;
    if (i < Ed) { g_count[i] = 0; g_count2[i] = 0; }
}

__global__ void __launch_bounds__(256) k_router(const float* __restrict__ x,
                                                const float* __restrict__ gw) {
    __shared__ float sgw[Ed * Hd];
    int tid = threadIdx.x;
    for (int i = tid; i < Ed * Hd; i += 256) sgw[i] = gw[i];
    __syncthreads();
    int warp = tid >> 5, lane = tid & 31;
    int t = blockIdx.x * 8 + warp;
    float acc[Ed];
#pragma unroll
    for (int e = 0; e < Ed; e++) acc[e] = 0.f;
    const float* xr = x + (size_t)t * Hd;
    for (int h = lane; h < Hd; h += 32) {
        float xv = xr[h];
#pragma unroll
        for (int e = 0; e < Ed; e++) acc[e] += xv * sgw[e * Hd + h];
    }
#pragma unroll
    for (int e = 0; e < Ed; e++) {
#pragma unroll
        for (int o = 16; o > 0; o >>= 1) acc[e] += __shfl_xor_sync(0xffffffffu, acc[e], o);
    }
    if (lane == 0) {
        float v0 = -1e30f; int e0 = 0;
#pragma unroll
        for (int e = 0; e < Ed; e++) if (acc[e] > v0) { v0 = acc[e]; e0 = e; }
        float v1 = -1e30f; int e1 = 0;
#pragma unroll
        for (int e = 0; e < Ed; e++) if (e != e0 && acc[e] > v1) { v1 = acc[e]; e1 = e; }
        float r  = expf(v1 - v0);
        float w0 = 1.f / (1.f + r);
        float w1 = r / (1.f + r);
        g_top_e[t * 2] = e0;  g_top_e[t * 2 + 1] = e1;
        g_top_w[t * 2] = w0;  g_top_w[t * 2 + 1] = w1;
        atomicAdd(&g_count[e0], 1);
        atomicAdd(&g_count[e1], 1);
    }
}

__global__ void k_scan() {
    int off = 0;
    for (int e = 0; e < Ed; e++) { g_offset[e] = off; off += g_count[e]; }
}

__global__ void __launch_bounds__(256) k_assign() {
    int t = blockIdx.x * 256 + threadIdx.x;
    if (t >= Tn) return;
#pragma unroll
    for (int k = 0; k < 2; k++) {
        int e   = g_top_e[t * 2 + k];
        int pos = atomicAdd(&g_count2[e], 1);
        int row = g_offset[e] + pos;
        g_row_tok[row]       = t;
        g_tok_row[t * 2 + k] = row;
    }
}

// ================= GEMM1: hidden = silu(x@wg^T) * (x@wu^T) =================
// CTA 128(m) x 64(n), K-chunk 32, 256 threads = 8 warps (4m x 2n), warp 32x32 dual.
// SMEM floats: toks[128] | per-buf { A 128x36, Bg 64x36, Bu 64x36 } x2
#define G1_BUF (128 * 36 + 64 * 36 + 64 * 36)        // 9216 floats
#define G1_SMEM ((128 + 2 * G1_BUF) * 4)             // 74240 B
__global__ void __launch_bounds__(256) k_gemm1(const float* __restrict__ x,
                                               const float* __restrict__ wg,
                                               const float* __restrict__ wu) {
    int e   = blockIdx.z;
    int cnt = g_count[e];
    int m0  = blockIdx.x * 128;
    if (m0 >= cnt) return;
    int off = g_offset[e];
    int n0  = blockIdx.y * 64;

    extern __shared__ float smf[];
    int* toks = (int*)smf;

    int tid = threadIdx.x;
    int lane = tid & 31, wid = tid >> 5;
    int warp_m = wid & 3, warp_n = wid >> 2;
    int g = lane >> 2, tig = lane & 3;

    for (int i = tid; i < 128; i += 256) {
        int m = m0 + i; if (m >= cnt) m = cnt - 1;
        toks[i] = g_row_tok[off + m];
    }
    __syncthreads();

    // gmem row pointers (hoisted; clamped rows read valid data, results discarded)
    const float* wgE = wg + (size_t)e * Id * Hd;
    const float* wuE = wu + (size_t)e * Id * Hd;
    const float* aptr[4]; const float* gptr[2]; const float* uptr[2];
#pragma unroll
    for (int p = 0; p < 4; p++) {
        int idx = tid + 256 * p;               // 0..1023
        int r = idx >> 3, c4 = (idx & 7) * 4;
        aptr[p] = x + (size_t)toks[r] * Hd + c4;
    }
#pragma unroll
    for (int p = 0; p < 2; p++) {
        int idx = tid + 256 * p;               // 0..511
        int r = idx >> 3, c4 = (idx & 7) * 4;
        gptr[p] = wgE + (size_t)(n0 + r) * Hd + c4;
        uptr[p] = wuE + (size_t)(n0 + r) * Hd + c4;
    }

    float cg[2][4][4] = {}, cu[2][4][4] = {};
    float4 rA[4], rG[2], rU[2];

    // prologue: chunk 0 -> buf 0
#pragma unroll
    for (int p = 0; p < 4; p++) rA[p] = *(const float4*)(aptr[p]);
#pragma unroll
    for (int p = 0; p < 2; p++) { rG[p] = *(const float4*)(gptr[p]); rU[p] = *(const float4*)(uptr[p]); }
    {
        float* A  = smf + 128;
        float* Bg = A + 128 * 36;
        float* Bu = Bg + 64 * 36;
#pragma unroll
        for (int p = 0; p < 4; p++) {
            int idx = tid + 256 * p; int r = idx >> 3, c4 = (idx & 7) * 4;
            *(uint4*)(A + r * 36 + c4) = tf4(rA[p]);
        }
#pragma unroll
        for (int p = 0; p < 2; p++) {
            int idx = tid + 256 * p; int r = idx >> 3, c4 = (idx & 7) * 4;
            *(uint4*)(Bg + r * 36 + c4) = tf4(rG[p]);
            *(uint4*)(Bu + r * 36 + c4) = tf4(rU[p]);
        }
    }
    __syncthreads();

    const int NCH = Hd / 32;  // 32
    for (int ch = 0; ch < NCH; ch++) {
        int buf = ch & 1;
        if (ch + 1 < NCH) {
            int k0 = (ch + 1) * 32;
#pragma unroll
            for (int p = 0; p < 4; p++) rA[p] = *(const float4*)(aptr[p] + k0);
#pragma unroll
            for (int p = 0; p < 2; p++) { rG[p] = *(const float4*)(gptr[p] + k0); rU[p] = *(const float4*)(uptr[p] + k0); }
        }
        const uint32_t* A  = (const uint32_t*)(smf + 128 + buf * G1_BUF);
        const uint32_t* Bg = A + 128 * 36;
        const uint32_t* Bu = Bg + 64 * 36;
#pragma unroll
        for (int ks = 0; ks < 4; ks++) {
            int kc = ks * 8;
            uint32_t a[2][4];
#pragma unroll
            for (int i = 0; i < 2; i++) {
                int r = warp_m * 32 + i * 16 + g;
                a[i][0] = A[r * 36 + kc + tig];
                a[i][1] = A[(r + 8) * 36 + kc + tig];
                a[i][2] = A[r * 36 + kc + tig + 4];
                a[i][3] = A[(r + 8) * 36 + kc + tig + 4];
            }
#pragma unroll
            for (int j = 0; j < 4; j++) {
                int n = warp_n * 32 + j * 8 + g;
                uint32_t bg0 = Bg[n * 36 + kc + tig], bg1 = Bg[n * 36 + kc + tig + 4];
                uint32_t bu0 = Bu[n * 36 + kc + tig], bu1 = Bu[n * 36 + kc + tig + 4];
#pragma unroll
                for (int i = 0; i < 2; i++) {
                    MMA_TF32(cg[i][j], a[i], bg0, bg1);
                    MMA_TF32(cu[i][j], a[i], bu0, bu1);
                }
            }
        }
        __syncthreads();
        if (ch + 1 < NCH) {
            float* An  = smf + 128 + (buf ^ 1) * G1_BUF;
            float* Bgn = An + 128 * 36;
            float* Bun = Bgn + 64 * 36;
#pragma unroll
            for (int p = 0; p < 4; p++) {
                int idx = tid + 256 * p; int r = idx >> 3, c4 = (idx & 7) * 4;
                *(uint4*)(An + r * 36 + c4) = tf4(rA[p]);
            }
#pragma unroll
            for (int p = 0; p < 2; p++) {
                int idx = tid + 256 * p; int r = idx >> 3, c4 = (idx & 7) * 4;
                *(uint4*)(Bgn + r * 36 + c4) = tf4(rG[p]);
                *(uint4*)(Bun + r * 36 + c4) = tf4(rU[p]);
            }
            __syncthreads();
        }
    }

    // epilogue: silu(gate)*up -> g_hidden
#pragma unroll
    for (int i = 0; i < 2; i++) {
        int rb = m0 + warp_m * 32 + i * 16 + g;
#pragma unroll
        for (int j = 0; j < 4; j++) {
            int n = n0 + warp_n * 32 + j * 8 + 2 * tig;
            if (rb < cnt) {
                size_t base = (size_t)(off + rb) * Id + n;
                float g0 = cg[i][j][0], g1 = cg[i][j][1];
                g_hidden[base]     = g0 / (1.f + expf(-g0)) * cu[i][j][0];
                g_hidden[base + 1] = g1 / (1.f + expf(-g1)) * cu[i][j][1];
            }
            if (rb + 8 < cnt) {
                size_t base = (size_t)(off + rb + 8) * Id + n;
                float g2 = cg[i][j][2], g3 = cg[i][j][3];
                g_hidden[base]     = g2 / (1.f + expf(-g2)) * cu[i][j][2];
                g_hidden[base + 1] = g3 / (1.f + expf(-g3)) * cu[i][j][3];
            }
        }
    }
}

// ================= GEMM2: down = hidden @ wd^T =================
// CTA 128(m) x 128(n), K-chunk 32, 256 threads = 8 warps (4m x 2n), warp 32x64.
// SMEM floats: per-buf { A 128x36, B 128x36 } x2
#define G2_BUF (128 * 36 * 2)                        // 9216 floats
#define G2_SMEM (2 * G2_BUF * 4)                     // 73728 B
__global__ void __launch_bounds__(256) k_gemm2(const float* __restrict__ wd) {
    int e   = blockIdx.z;
    int cnt = g_count[e];
    int m0  = blockIdx.x * 128;
    if (m0 >= cnt) return;
    int off = g_offset[e];
    int n0  = blockIdx.y * 128;

    extern __shared__ float smf[];

    int tid = threadIdx.x;
    int lane = tid & 31, wid = tid >> 5;
    int warp_m = wid & 3, warp_n = wid >> 2;
    int g = lane >> 2, tig = lane & 3;

    const float* wdE = wd + (size_t)e * Hd * Id;
    const float* aptr[4]; const float* bptr[4];
#pragma unroll
    for (int p = 0; p < 4; p++) {
        int idx = tid + 256 * p;               // 0..1023
        int r = idx >> 3, c4 = (idx & 7) * 4;
        int am = m0 + r; if (am >= cnt) am = cnt - 1;
        aptr[p] = g_hidden + (size_t)(off + am) * Id + c4;
        bptr[p] = wdE + (size_t)(n0 + r) * Id + c4;
    }

    float c[2][8][4] = {};
    float4 rA[4], rB[4];

#pragma unroll
    for (int p = 0; p < 4; p++) { rA[p] = *(const float4*)(aptr[p]); rB[p] = *(const float4*)(bptr[p]); }
    {
        float* A = smf;
        float* B = A + 128 * 36;
#pragma unroll
        for (int p = 0; p < 4; p++) {
            int idx = tid + 256 * p; int r = idx >> 3, c4 = (idx & 7) * 4;
            *(uint4*)(A + r * 36 + c4) = tf4(rA[p]);
            *(uint4*)(B + r * 36 + c4) = tf4(rB[p]);
        }
    }
    __syncthreads();

    const int NCH = Id / 32;  // 128
    for (int ch = 0; ch < NCH; ch++) {
        int buf = ch & 1;
        if (ch + 1 < NCH) {
            int k0 = (ch + 1) * 32;
#pragma unroll
            for (int p = 0; p < 4; p++) { rA[p] = *(const float4*)(aptr[p] + k0); rB[p] = *(const float4*)(bptr[p] + k0); }
        }
        const uint32_t* A = (const uint32_t*)(smf + buf * G2_BUF);
        const uint32_t* B = A + 128 * 36;
#pragma unroll
        for (int ks = 0; ks < 4; ks++) {
            int kc = ks * 8;
            uint32_t a[2][4];
#pragma unroll
            for (int i = 0; i < 2; i++) {
                int r = warp_m * 32 + i * 16 + g;
                a[i][0] = A[r * 36 + kc + tig];
                a[i][1] = A[(r + 8) * 36 + kc + tig];
                a[i][2] = A[r * 36 + kc + tig + 4];
                a[i][3] = A[(r + 8) * 36 + kc + tig + 4];
            }
#pragma unroll
            for (int j = 0; j < 8; j++) {
                int n = warp_n * 64 + j * 8 + g;
                uint32_t b0 = B[n * 36 + kc + tig], b1 = B[n * 36 + kc + tig + 4];
#pragma unroll
                for (int i = 0; i < 2; i++) MMA_TF32(c[i][j], a[i], b0, b1);
            }
        }
        __syncthreads();
        if (ch + 1 < NCH) {
            float* An = smf + (buf ^ 1) * G2_BUF;
            float* Bn = An + 128 * 36;
#pragma unroll
            for (int p = 0; p < 4; p++) {
                int idx = tid + 256 * p; int r = idx >> 3, c4 = (idx & 7) * 4;
                *(uint4*)(An + r * 36 + c4) = tf4(rA[p]);
                *(uint4*)(Bn + r * 36 + c4) = tf4(rB[p]);
            }
            __syncthreads();
        }
    }

#pragma unroll
    for (int i = 0; i < 2; i++) {
        int rb = m0 + warp_m * 32 + i * 16 + g;
#pragma unroll
        for (int j = 0; j < 8; j++) {
            int n = n0 + warp_n * 64 + j * 8 + 2 * tig;
            if (rb < cnt) {
                size_t base = (size_t)(off + rb) * Hd + n;
                g_down[base]     = c[i][j][0];
                g_down[base + 1] = c[i][j][1];
            }
            if (rb + 8 < cnt) {
                size_t base = (size_t)(off + rb + 8) * Hd + n;
                g_down[base]     = c[i][j][2];
                g_down[base + 1] = c[i][j][3];
            }
        }
    }
}

// ---------------- combine ----------------
__global__ void __launch_bounds__(256) k_combine(float* __restrict__ out) {
    int idx = blockIdx.x * 256 + threadIdx.x;
    int t   = idx >> 8;
    int c4  = (idx & 255) << 2;
    int r0  = g_tok_row[t * 2];
    int r1  = g_tok_row[t * 2 + 1];
    float w0 = g_top_w[t * 2];
    float w1 = g_top_w[t * 2 + 1];
    float4 d0 = *(const float4*)(g_down + (size_t)r0 * Hd + c4);
    float4 d1 = *(const float4*)(g_down + (size_t)r1 * Hd + c4);
    float4 o;
    o.x = w0 * d0.x + w1 * d1.x;
    o.y = w0 * d0.y + w1 * d1.y;
    o.z = w0 * d0.z + w1 * d1.z;
    o.w = w0 * d0.w + w1 * d1.w;
    *(float4*)(out + (size_t)t * Hd + c4) = o;
}

// ---------------- launch ----------------
extern "C" void kernel_launch(void* const* d_in, const int* in_sizes, int n_in,
                              void* d_out, int out_size) {
    const float* x  = (const float*)d_in[0];
    const float* gw = (const float*)d_in[1];
    const float* wg = (const float*)d_in[2];
    const float* wu = (const float*)d_in[3];
    const float* wd = (const float*)d_in[4];
    float* out = (float*)d_out;

    cudaFuncSetAttribute(k_gemm1, cudaFuncAttributeMaxDynamicSharedMemorySize, G1_SMEM);
    cudaFuncSetAttribute(k_gemm2, cudaFuncAttributeMaxDynamicSharedMemorySize, G2_SMEM);

    k_init<<<1, 32>>>();
    k_router<<<Tn / 8, 256>>>(x, gw);
    k_scan<<<1, 1>>>();
    k_assign<<<Tn / 256, 256>>>();

    dim3 g1(32, 64, Ed);   // m-tiles(128) x n-tiles(64 over I) x experts (early-exit)
    k_gemm1<<<g1, 256, G1_SMEM>>>(x, wg, wu);

    dim3 g2(32, 8, Ed);    // m-tiles(128) x n-tiles(128 over H) x experts (early-exit)
    k_gemm2<<<g2, 256, G2_SMEM>>>(wd);

    k_combine<<<Tn * Hd / 1024, 256>>>(out);
}